// round 12
// baseline (speedup 1.0000x reference)
#include <cuda_runtime.h>
#include <cstdint>

#define Tq   1024
#define F_IN 64
#define HDIM 40
#define G4   160

typedef unsigned long long ull;

// ---- global scratch (no allocation allowed; __device__ arrays) ----
__device__ float g_xa[(size_t)512 * Tq * G4];     // seq @ WaK + ba
__device__ float g_xb[(size_t)512 * Tq * G4];     // hs  @ WbK + bb
__device__ float g_hs[(size_t)512 * Tq * HDIM];   // LSTM A outputs
__device__ float g_hlast[512 * HDIM];             // LSTM B final h

// ---------------------------------------------------------------------------
// Packed f32x2 helpers
// ---------------------------------------------------------------------------
__device__ __forceinline__ ull pack2(float a, float b) {
    ull r; asm("mov.b64 %0, {%1,%2};" : "=l"(r) : "f"(a), "f"(b)); return r;
}
__device__ __forceinline__ void unpack2(ull v, float& a, float& b) {
    asm("mov.b64 {%0,%1}, %2;" : "=f"(a), "=f"(b) : "l"(v));
}
__device__ __forceinline__ void ffma2(ull& d, ull a, ull b) {
    asm("fma.rn.f32x2 %0, %1, %2, %0;" : "+l"(d) : "l"(a), "l"(b));
}
__device__ __forceinline__ ull addx2(ull a, ull b) {
    ull r; asm("add.rn.f32x2 %0, %1, %2;" : "=l"(r) : "l"(a), "l"(b)); return r;
}

// ---------------------------------------------------------------------------
// MUFU activations
// ---------------------------------------------------------------------------
__device__ __forceinline__ float sigmoid_f(float x) {
    float e, r;
    asm("ex2.approx.f32 %0, %1;" : "=f"(e) : "f"(-1.4426950408889634f * x));
    asm("rcp.approx.f32 %0, %1;" : "=f"(r) : "f"(1.0f + e));
    return r;
}
__device__ __forceinline__ float tanh_f(float x) {
    float e, r;
    asm("ex2.approx.f32 %0, %1;" : "=f"(e) : "f"(2.8853900817779268f * x));
    asm("rcp.approx.f32 %0, %1;" : "=f"(r) : "f"(1.0f + e));
    return 1.0f - 2.0f * r;
}
__device__ __forceinline__ float gate_act(float z, float mm, float aa, float bb) {
    float e, r;
    asm("ex2.approx.f32 %0, %1;" : "=f"(e) : "f"(mm * z));
    asm("rcp.approx.f32 %0, %1;" : "=f"(r) : "f"(1.0f + e));
    return fmaf(aa, r, bb);
}

__device__ __forceinline__ unsigned smem_u32(const void* p) {
    return (unsigned)__cvta_generic_to_shared(p);
}

// ===========================================================================
// K1: xa[b,t,g] = seq[b,t,:]·WaK[:,g] + ba[g].  (verified R10: smem staging)
// ===========================================================================
__global__ void __launch_bounds__(160)
xa_gemm(const float* __restrict__ seq, const float* __restrict__ WaK,
        const float* __restrict__ ba)
{
    __shared__ __align__(16) float4 sx[32 * 16];   // 32 rows x 64 floats = 8KB
    const int b = blockIdx.x, ch = blockIdx.y, g = threadIdx.x;

    ull wk2[32];
    #pragma unroll
    for (int p = 0; p < 32; p++)
        wk2[p] = pack2(WaK[(2 * p) * G4 + g], WaK[(2 * p + 1) * G4 + g]);
    const float bias = ba[g];

    const size_t base = (size_t)b * Tq + (size_t)ch * 256;
    const float4* src = (const float4*)(seq + base * F_IN);
    float* op = g_xa + base * G4 + g;

    for (int tile = 0; tile < 8; tile++) {
        const float4* s4 = src + (size_t)tile * 512;
        #pragma unroll
        for (int i = 0; i < 4; i++) {
            const int idx = g + i * 160;
            if (idx < 512) sx[idx] = s4[idx];
        }
        __syncthreads();

        #pragma unroll 2
        for (int r = 0; r < 32; r += 2) {
            const ulonglong2* r0 = (const ulonglong2*)&sx[r * 16];
            const ulonglong2* r1 = (const ulonglong2*)&sx[(r + 1) * 16];
            ull a0 = 0, a1 = 0, c0 = 0, c1 = 0;
            #pragma unroll
            for (int p = 0; p < 16; p++) {
                ulonglong2 v0 = r0[p], v1 = r1[p];
                ffma2(a0, wk2[2 * p],     v0.x);
                ffma2(a1, wk2[2 * p + 1], v0.y);
                ffma2(c0, wk2[2 * p],     v1.x);
                ffma2(c1, wk2[2 * p + 1], v1.y);
            }
            float x0, x1, x2, x3;
            unpack2(a0, x0, x1); unpack2(a1, x2, x3);
            op[(size_t)(tile * 32 + r) * G4] = bias + ((x0 + x2) + (x1 + x3));
            unpack2(c0, x0, x1); unpack2(c1, x2, x3);
            op[(size_t)(tile * 32 + r + 1) * G4] = bias + ((x0 + x2) + (x1 + x3));
        }
        __syncthreads();
    }
}

// ===========================================================================
// K3: xb[b,t,g] = hs[b,t,:]·WbK[:,g] + bb[g].  (verified R10)
// ===========================================================================
__global__ void __launch_bounds__(160)
xb_gemm(const float* __restrict__ WbK, const float* __restrict__ bb)
{
    __shared__ __align__(16) float4 sh4[64 * 10];  // 64 rows x 40 floats = 10KB
    const int b = blockIdx.x, ch = blockIdx.y, g = threadIdx.x;

    ull wk2[20];
    #pragma unroll
    for (int p = 0; p < 20; p++)
        wk2[p] = pack2(WbK[(2 * p) * G4 + g], WbK[(2 * p + 1) * G4 + g]);
    const float bias = bb[g];

    const size_t base = (size_t)b * Tq + (size_t)ch * 256;
    const float4* src = (const float4*)(g_hs + base * HDIM);
    float* op = g_xb + base * G4 + g;

    for (int tile = 0; tile < 4; tile++) {
        const float4* s4 = src + (size_t)tile * 640;
        #pragma unroll
        for (int i = 0; i < 4; i++) sh4[g + i * 160] = s4[g + i * 160];
        __syncthreads();

        #pragma unroll 2
        for (int r = 0; r < 64; r += 2) {
            const ulonglong2* r0 = (const ulonglong2*)&sh4[r * 10];
            const ulonglong2* r1 = (const ulonglong2*)&sh4[(r + 1) * 10];
            ull a0 = 0, a1 = 0, c0 = 0, c1 = 0;
            #pragma unroll
            for (int p = 0; p < 10; p++) {
                ulonglong2 v0 = r0[p], v1 = r1[p];
                ffma2(a0, wk2[2 * p],     v0.x);
                ffma2(a1, wk2[2 * p + 1], v0.y);
                ffma2(c0, wk2[2 * p],     v1.x);
                ffma2(c1, wk2[2 * p + 1], v1.y);
            }
            float x0, x1, x2, x3;
            unpack2(a0, x0, x1); unpack2(a1, x2, x3);
            op[(size_t)(tile * 64 + r) * G4] = bias + ((x0 + x2) + (x1 + x3));
            unpack2(c0, x0, x1); unpack2(c1, x2, x3);
            op[(size_t)(tile * 64 + r + 1) * G4] = bias + ((x0 + x2) + (x1 + x3));
        }
        __syncthreads();
    }
}

// ===========================================================================
// K2/K4: LSTM recurrence, 2 warps per row, ONE block barrier per step.
// grid 512, block 64. Warp w owns cols [80w, 80w+80): lane l computes
// c0=80w+l, c1=c0+32, c2=(c0+64) mod 160 (the mod makes work uniform; the
// ~16 wrapped columns are computed by both warps with IDENTICAL values, so
// the duplicate sv stores are benign).
// After the barrier, BOTH warps redundantly run the full c/h update into a
// warp-PRIVATE h copy sh[w][40] — h ordering becomes intra-warp (__syncwarp),
// eliminating the second block barrier. sv is double-buffered vs the race
// where a fast warp's next-step sv stores overlap a slow warp's update reads.
// MODE 0: g_xa -> g_hs (warp0 stores).  MODE 1: g_xb -> g_hlast.
// ===========================================================================
template<int MODE>
__global__ void __launch_bounds__(64)
recur_k(const float* __restrict__ Wr)
{
    __shared__ __align__(16) float sxa[8][G4];     // cp.async ring (5KB)
    __shared__ __align__(16) float sv[2][G4];      // act exchange, dbl-buffered
    __shared__ __align__(16) float sh[2][HDIM];    // warp-PRIVATE h copies

    const int b = blockIdx.x, tid = threadIdx.x;
    const int w = tid >> 5, l = tid & 31;

    const int c0 = 80 * w + l;
    const int c1 = c0 + 32;
    int c2 = c0 + 64; if (c2 >= G4) c2 -= G4;

    // per-column activation constants (tanh for g-gate cols 80..119)
    const float L1 = -1.4426950408889634f, L2 = -2.8853900817779268f;
    const bool g0 = (c0 >= 80 && c0 < 120), g1 = (c1 >= 80 && c1 < 120),
               g2 = (c2 >= 80 && c2 < 120);
    const float mm0 = g0 ? L2 : L1, aa0 = g0 ? 2.f : 1.f, bb0 = g0 ? -1.f : 0.f;
    const float mm1 = g1 ? L2 : L1, aa1 = g1 ? 2.f : 1.f, bb1 = g1 ? -1.f : 0.f;
    const float mm2 = g2 ? L2 : L1, aa2 = g2 ? 2.f : 1.f, bb2 = g2 ? -1.f : 0.f;

    // weights: 3 columns x 20 f32x2 pairs in registers
    ull w0r[20], w1r[20], w2r[20];
    #pragma unroll
    for (int p = 0; p < 20; p++) {
        w0r[p] = pack2(Wr[(2 * p) * G4 + c0], Wr[(2 * p + 1) * G4 + c0]);
        w1r[p] = pack2(Wr[(2 * p) * G4 + c1], Wr[(2 * p + 1) * G4 + c1]);
        w2r[p] = pack2(Wr[(2 * p) * G4 + c2], Wr[(2 * p + 1) * G4 + c2]);
    }

    float cs1 = 0.0f, cs2 = 0.0f;      // c-state: unit l, and unit 32+l (l<8)
    sh[w][l] = 0.0f;
    if (l < 8) sh[w][32 + l] = 0.0f;

    const float* xsrc = (MODE == 0 ? g_xa : g_xb) + (size_t)b * Tq * G4;

    // ring prologue: 40 chunks of 16B per row; loaders = lanes 0..19 per warp
    const bool isLd = (l < 20);
    const int cc = (w * 20 + l) * 4;   // float offset of this thread's chunk
    if (isLd) {
        #pragma unroll
        for (int p = 0; p < 5; p++) {
            unsigned dst = smem_u32(&sxa[p][cc]);
            asm volatile("cp.async.ca.shared.global [%0], [%1], 16;\n\t"
                         "cp.async.commit_group;\n"
                         :: "r"(dst), "l"(xsrc + (size_t)p * G4 + cc));
        }
        asm volatile("cp.async.wait_group 4;");   // slot 0 ready
    }
    __syncthreads();

    for (int t = 0; t < Tq; t++) {
        // ---- dots for 3 columns over own h copy (6 indep FFMA2 chains) ----
        const float xz0 = sxa[t & 7][c0];
        const float xz1 = sxa[t & 7][c1];
        const float xz2 = sxa[t & 7][c2];
        const ulonglong2* h2 = (const ulonglong2*)sh[w];
        ull a0 = 0, a1 = 0, e0 = 0, e1 = 0, d0 = 0, d1 = 0;
        #pragma unroll
        for (int p = 0; p < 10; p++) {
            ulonglong2 hv = h2[p];
            ffma2(a0, w0r[2 * p],     hv.x);
            ffma2(a1, w0r[2 * p + 1], hv.y);
            ffma2(e0, w1r[2 * p],     hv.x);
            ffma2(e1, w1r[2 * p + 1], hv.y);
            ffma2(d0, w2r[2 * p],     hv.x);
            ffma2(d1, w2r[2 * p + 1], hv.y);
        }
        float lo, hi;
        unpack2(addx2(a0, a1), lo, hi); const float z0 = xz0 + lo + hi;
        unpack2(addx2(e0, e1), lo, hi); const float z1 = xz1 + lo + hi;
        unpack2(addx2(d0, d1), lo, hi); const float z2 = xz2 + lo + hi;
        const float v0 = gate_act(z0, mm0, aa0, bb0);
        const float v1 = gate_act(z1, mm1, aa1, bb1);
        const float v2 = gate_act(z2, mm2, aa2, bb2);

        // ---- ring: prefetch slot t+5, guarantee slot t+1 (before the bar) ----
        if (isLd) {
            const int tf = t + 5;
            if (tf < Tq) {
                unsigned dst = smem_u32(&sxa[tf & 7][cc]);
                asm volatile("cp.async.ca.shared.global [%0], [%1], 16;"
                             :: "r"(dst), "l"(xsrc + (size_t)tf * G4 + cc));
            }
            asm volatile("cp.async.commit_group;\n\t"
                         "cp.async.wait_group 4;\n");
        }

        // ---- exchange activations ----
        float* svb = sv[t & 1];
        svb[c0] = v0; svb[c1] = v1; svb[c2] = v2;
        __syncthreads();

        // ---- update (BOTH warps, redundant, into own h copy) ----
        {
            const float iv = svb[l],      fv = svb[40 + l],
                        gv = svb[80 + l], ov = svb[120 + l];
            cs1 = fmaf(fv, cs1, iv * gv);
            const float h1 = ov * tanh_f(cs1);
            sh[w][l] = h1;
            if (MODE == 0) {
                if (w == 0) g_hs[((size_t)b * Tq + t) * HDIM + l] = h1;
            } else if (t == Tq - 1 && w == 0) {
                g_hlast[b * HDIM + l] = h1;
            }
            if (l < 8) {
                const int j2 = 32 + l;
                const float iw = svb[j2],      fw = svb[40 + j2],
                            gw = svb[80 + j2], ow = svb[120 + j2];
                cs2 = fmaf(fw, cs2, iw * gw);
                const float h2v = ow * tanh_f(cs2);
                sh[w][j2] = h2v;
                if (MODE == 0) {
                    if (w == 0) g_hs[((size_t)b * Tq + t) * HDIM + j2] = h2v;
                } else if (t == Tq - 1 && w == 0) {
                    g_hlast[b * HDIM + j2] = h2v;
                }
            }
        }
        __syncwarp();
    }
}

// ===========================================================================
// K5: dense tail. grid 128 x 160 threads, 4 rows/block.  (verified R10)
// ===========================================================================
__global__ void __launch_bounds__(160)
tail_k(const float* __restrict__ feat,
       const float* __restrict__ Wg, const float* __restrict__ bg,
       const float* __restrict__ Wh, const float* __restrict__ bh,
       const float* __restrict__ Wc, const float* __restrict__ bc,
       const float* __restrict__ Wd, const float* __restrict__ bd,
       const float* __restrict__ Wo, const float* __restrict__ bo,
       float* __restrict__ out)
{
    __shared__ float hB[4][HDIM];
    __shared__ float t1[4][10], yy[4][10], cc[4][20], dd[4][10];
    const int tid = threadIdx.x, b4 = blockIdx.x * 4;
    const int r = tid / HDIM, uu = tid % HDIM;

    hB[r][uu] = g_hlast[(b4 + r) * HDIM + uu];
    __syncthreads();

    const float* fb = feat + (size_t)(b4 + r) * F_IN;
    if (uu < 10) {
        float a = bg[uu];
        #pragma unroll 8
        for (int k = 0; k < F_IN; k++) a = fmaf(fb[k], Wg[k * 10 + uu], a);
        t1[r][uu] = tanh_f(a);
    }
    __syncthreads();
    if (uu < 10) {
        float a = bh[uu];
        #pragma unroll
        for (int k = 0; k < 10; k++) a = fmaf(t1[r][k], Wh[k * 10 + uu], a);
        yy[r][uu] = tanh_f(a);
    }
    __syncthreads();
    if (uu < 20) {
        float a = bc[uu];
        #pragma unroll
        for (int k = 0; k < HDIM; k++) a = fmaf(hB[r][k], Wc[k * 20 + uu], a);
        #pragma unroll
        for (int k = 0; k < 10; k++)   a = fmaf(yy[r][k], Wc[(HDIM + k) * 20 + uu], a);
        cc[r][uu] = fmaxf(a, 0.0f);
    }
    __syncthreads();
    if (uu < 10) {
        float a = bd[uu];
        #pragma unroll
        for (int k = 0; k < 20; k++) a = fmaf(cc[r][k], Wd[k * 10 + uu], a);
        dd[r][uu] = fmaxf(a, 0.0f);
    }
    __syncthreads();
    if (uu == 0) {
        float a = bo[0];
        #pragma unroll
        for (int k = 0; k < 10; k++) a = fmaf(dd[r][k], Wo[k], a);
        out[b4 + r] = sigmoid_f(a);
    }
}

// ---------------------------------------------------------------------------
extern "C" void kernel_launch(void* const* d_in, const int* in_sizes, int n_in,
                              void* d_out, int out_size)
{
    (void)in_sizes; (void)n_in; (void)out_size;
    const float* seq  = (const float*)d_in[0];
    const float* feat = (const float*)d_in[1];
    const float* WaK  = (const float*)d_in[2];
    const float* WaR  = (const float*)d_in[3];
    const float* ba   = (const float*)d_in[4];
    const float* WbK  = (const float*)d_in[5];
    const float* WbR  = (const float*)d_in[6];
    const float* bb   = (const float*)d_in[7];
    const float* Wg   = (const float*)d_in[8];
    const float* bg   = (const float*)d_in[9];
    const float* Wh   = (const float*)d_in[10];
    const float* bh   = (const float*)d_in[11];
    const float* Wc   = (const float*)d_in[12];
    const float* bc   = (const float*)d_in[13];
    const float* Wd   = (const float*)d_in[14];
    const float* bd   = (const float*)d_in[15];
    const float* Wo   = (const float*)d_in[16];
    const float* bo   = (const float*)d_in[17];
    float* out = (float*)d_out;

    xa_gemm<<<dim3(512, 4), 160>>>(seq, WaK, ba);
    recur_k<0><<<512, 64>>>(WaR);
    xb_gemm<<<dim3(512, 4), 160>>>(WbK, bb);
    recur_k<1><<<512, 64>>>(WbR);
    tail_k<<<128, 160>>>(feat, Wg, bg, Wh, bh, Wc, bc, Wd, bd, Wo, bo, out);
}

// round 13
// speedup vs baseline: 1.1581x; 1.1581x over previous
#include <cuda_runtime.h>
#include <cstdint>

#define Tq   1024
#define F_IN 64
#define HDIM 40
#define G4   160

typedef unsigned long long ull;

// ---- global scratch (no allocation allowed; __device__ arrays) ----
__device__ float g_xa[(size_t)512 * Tq * G4];     // seq @ WaK + ba
__device__ float g_xb[(size_t)512 * Tq * G4];     // hs  @ WbK + bb
__device__ float g_hs[(size_t)512 * Tq * HDIM];   // LSTM A outputs

// ---------------------------------------------------------------------------
// Packed f32x2 helpers
// ---------------------------------------------------------------------------
__device__ __forceinline__ ull pack2(float a, float b) {
    ull r; asm("mov.b64 %0, {%1,%2};" : "=l"(r) : "f"(a), "f"(b)); return r;
}
__device__ __forceinline__ void unpack2(ull v, float& a, float& b) {
    asm("mov.b64 {%0,%1}, %2;" : "=f"(a), "=f"(b) : "l"(v));
}
__device__ __forceinline__ void ffma2(ull& d, ull a, ull b) {
    asm("fma.rn.f32x2 %0, %1, %2, %0;" : "+l"(d) : "l"(a), "l"(b));
}

// ---------------------------------------------------------------------------
// MUFU activations
// ---------------------------------------------------------------------------
__device__ __forceinline__ float sigmoid_f(float x) {
    float e, r;
    asm("ex2.approx.f32 %0, %1;" : "=f"(e) : "f"(-1.4426950408889634f * x));
    asm("rcp.approx.f32 %0, %1;" : "=f"(r) : "f"(1.0f + e));
    return r;
}
__device__ __forceinline__ float tanh_f(float x) {
    float e, r;
    asm("ex2.approx.f32 %0, %1;" : "=f"(e) : "f"(2.8853900817779268f * x));
    asm("rcp.approx.f32 %0, %1;" : "=f"(r) : "f"(1.0f + e));
    return 1.0f - 2.0f * r;
}
__device__ __forceinline__ float gate_act(float z, float mm, float aa, float bb) {
    float e, r;
    asm("ex2.approx.f32 %0, %1;" : "=f"(e) : "f"(mm * z));
    asm("rcp.approx.f32 %0, %1;" : "=f"(r) : "f"(1.0f + e));
    return fmaf(aa, r, bb);
}

__device__ __forceinline__ unsigned smem_u32(const void* p) {
    return (unsigned)__cvta_generic_to_shared(p);
}

// ===========================================================================
// K1: xa[b,t,g] = seq[b,t,:]·WaK[:,g] + ba[g].
// v2: 80 threads, 2 cols/thread (g, g+80), 2 rows in flight -> 8 FFMA2
// chains per 2 LDS.128, halving smem-crossbar pressure vs R10 (which had 5
// warps all re-reading every x row). Weights (2 cols) in registers.
// ===========================================================================
__global__ void __launch_bounds__(80)
xa_gemm(const float* __restrict__ seq, const float* __restrict__ WaK,
        const float* __restrict__ ba)
{
    __shared__ __align__(16) float4 sx[32 * 16];   // 32 rows x 64 floats = 8KB
    const int b = blockIdx.x, ch = blockIdx.y, g0 = threadIdx.x, g1 = g0 + 80;

    ull wA[32], wB[32];
    #pragma unroll
    for (int p = 0; p < 32; p++) {
        wA[p] = pack2(WaK[(2 * p) * G4 + g0], WaK[(2 * p + 1) * G4 + g0]);
        wB[p] = pack2(WaK[(2 * p) * G4 + g1], WaK[(2 * p + 1) * G4 + g1]);
    }
    const float bias0 = ba[g0], bias1 = ba[g1];

    const size_t base = (size_t)b * Tq + (size_t)ch * 256;
    const float4* src = (const float4*)(seq + base * F_IN);
    float* op0 = g_xa + base * G4 + g0;
    float* op1 = g_xa + base * G4 + g1;

    for (int tile = 0; tile < 8; tile++) {
        const float4* s4 = src + (size_t)tile * 512;
        for (int idx = g0; idx < 512; idx += 80) sx[idx] = s4[idx];
        __syncthreads();

        for (int r = 0; r < 32; r += 2) {
            const ulonglong2* r0 = (const ulonglong2*)&sx[r * 16];
            const ulonglong2* r1 = (const ulonglong2*)&sx[(r + 1) * 16];
            ull a0 = 0, a1 = 0, b0 = 0, b1 = 0, c0 = 0, c1 = 0, d0 = 0, d1 = 0;
            #pragma unroll
            for (int p = 0; p < 16; p++) {
                ulonglong2 v0 = r0[p], v1 = r1[p];
                ffma2(a0, wA[2 * p],     v0.x);
                ffma2(a1, wA[2 * p + 1], v0.y);
                ffma2(b0, wA[2 * p],     v1.x);
                ffma2(b1, wA[2 * p + 1], v1.y);
                ffma2(c0, wB[2 * p],     v0.x);
                ffma2(c1, wB[2 * p + 1], v0.y);
                ffma2(d0, wB[2 * p],     v1.x);
                ffma2(d1, wB[2 * p + 1], v1.y);
            }
            const int t = tile * 32 + r;
            float x0, x1, x2, x3;
            unpack2(a0, x0, x1); unpack2(a1, x2, x3);
            op0[(size_t)t * G4]       = bias0 + ((x0 + x2) + (x1 + x3));
            unpack2(b0, x0, x1); unpack2(b1, x2, x3);
            op0[(size_t)(t + 1) * G4] = bias0 + ((x0 + x2) + (x1 + x3));
            unpack2(c0, x0, x1); unpack2(c1, x2, x3);
            op1[(size_t)t * G4]       = bias1 + ((x0 + x2) + (x1 + x3));
            unpack2(d0, x0, x1); unpack2(d1, x2, x3);
            op1[(size_t)(t + 1) * G4] = bias1 + ((x0 + x2) + (x1 + x3));
        }
        __syncthreads();
    }
}

// ===========================================================================
// K3: xb[b,t,g] = hs[b,t,:]·WbK[:,g] + bb[g].  Same v2 design, 40-long dots.
// ===========================================================================
__global__ void __launch_bounds__(80)
xb_gemm(const float* __restrict__ WbK, const float* __restrict__ bb)
{
    __shared__ __align__(16) float4 sh4[64 * 10];  // 64 rows x 40 floats = 10KB
    const int b = blockIdx.x, ch = blockIdx.y, g0 = threadIdx.x, g1 = g0 + 80;

    ull wA[20], wB[20];
    #pragma unroll
    for (int p = 0; p < 20; p++) {
        wA[p] = pack2(WbK[(2 * p) * G4 + g0], WbK[(2 * p + 1) * G4 + g0]);
        wB[p] = pack2(WbK[(2 * p) * G4 + g1], WbK[(2 * p + 1) * G4 + g1]);
    }
    const float bias0 = bb[g0], bias1 = bb[g1];

    const size_t base = (size_t)b * Tq + (size_t)ch * 256;
    const float4* src = (const float4*)(g_hs + base * HDIM);
    float* op0 = g_xb + base * G4 + g0;
    float* op1 = g_xb + base * G4 + g1;

    for (int tile = 0; tile < 4; tile++) {
        const float4* s4 = src + (size_t)tile * 640;
        #pragma unroll
        for (int i = 0; i < 8; i++) sh4[g0 + i * 80] = s4[g0 + i * 80];
        __syncthreads();

        for (int r = 0; r < 64; r += 2) {
            const ulonglong2* r0 = (const ulonglong2*)&sh4[r * 10];
            const ulonglong2* r1 = (const ulonglong2*)&sh4[(r + 1) * 10];
            ull a0 = 0, a1 = 0, b0 = 0, b1 = 0, c0 = 0, c1 = 0, d0 = 0, d1 = 0;
            #pragma unroll
            for (int p = 0; p < 10; p++) {
                ulonglong2 v0 = r0[p], v1 = r1[p];
                ffma2(a0, wA[2 * p],     v0.x);
                ffma2(a1, wA[2 * p + 1], v0.y);
                ffma2(b0, wA[2 * p],     v1.x);
                ffma2(b1, wA[2 * p + 1], v1.y);
                ffma2(c0, wB[2 * p],     v0.x);
                ffma2(c1, wB[2 * p + 1], v0.y);
                ffma2(d0, wB[2 * p],     v1.x);
                ffma2(d1, wB[2 * p + 1], v1.y);
            }
            const int t = tile * 64 + r;
            float x0, x1, x2, x3;
            unpack2(a0, x0, x1); unpack2(a1, x2, x3);
            op0[(size_t)t * G4]       = bias0 + ((x0 + x2) + (x1 + x3));
            unpack2(b0, x0, x1); unpack2(b1, x2, x3);
            op0[(size_t)(t + 1) * G4] = bias0 + ((x0 + x2) + (x1 + x3));
            unpack2(c0, x0, x1); unpack2(c1, x2, x3);
            op1[(size_t)t * G4]       = bias1 + ((x0 + x2) + (x1 + x3));
            unpack2(d0, x0, x1); unpack2(d1, x2, x3);
            op1[(size_t)(t + 1) * G4] = bias1 + ((x0 + x2) + (x1 + x3));
        }
        __syncthreads();
    }
}

// ===========================================================================
// K2: LSTM A recurrence — byte-identical logic to R10's recur_k<0> (453us,
// verified local optimum: 160thr/512blk, 17 warps/SM).
// ===========================================================================
__global__ void __launch_bounds__(160)
recur_a(const float* __restrict__ Wr)
{
    __shared__ __align__(16) float sxa[8][G4];
    __shared__ __align__(16) float sh[2][HDIM];

    const int b = blockIdx.x, tid = threadIdx.x;
    const int lane = tid & 31, q = lane >> 3, u = lane & 7, w = tid >> 5;
    const int j = w * 8 + u;
    const int col = q * HDIM + j;

    const bool isG = (q == 2);
    const float mm  = isG ? -2.8853900817779268f : -1.4426950408889634f;
    const float aa  = isG ? 2.0f : 1.0f;
    const float bbv = isG ? -1.0f : 0.0f;

    ull wr2[20];
    #pragma unroll
    for (int p = 0; p < 20; p++)
        wr2[p] = pack2(Wr[(2 * p) * G4 + col], Wr[(2 * p + 1) * G4 + col]);

    float c = 0.0f;
    if (tid < HDIM) sh[0][tid] = 0.0f;

    const float* srcb = g_xa + (size_t)b * Tq * G4;

    if (tid < 40) {
        #pragma unroll
        for (int p = 0; p < 4; p++) {
            unsigned dst = smem_u32(&sxa[p][tid * 4]);
            asm volatile("cp.async.ca.shared.global [%0], [%1], 16;\n\t"
                         "cp.async.commit_group;\n"
                         :: "r"(dst), "l"(srcb + (size_t)p * G4 + tid * 4));
        }
        asm volatile("cp.async.wait_group 3;");
    }
    __syncthreads();

    for (int t = 0; t < Tq; t++) {
        if (tid < 40) {
            const int tf = t + 4;
            if (tf < Tq) {
                unsigned dst = smem_u32(&sxa[tf & 7][tid * 4]);
                asm volatile("cp.async.ca.shared.global [%0], [%1], 16;"
                             :: "r"(dst), "l"(srcb + (size_t)tf * G4 + tid * 4));
            }
            asm volatile("cp.async.commit_group;\n\t"
                         "cp.async.wait_group 3;\n");
        }

        const float xz = sxa[t & 7][col];
        const ulonglong2* h2 = (const ulonglong2*)sh[t & 1];
        ull a0 = 0ull, a1 = 0ull;
        #pragma unroll
        for (int p = 0; p < 10; p++) {
            ulonglong2 hv = h2[p];
            ffma2(a0, wr2[2 * p],     hv.x);
            ffma2(a1, wr2[2 * p + 1], hv.y);
        }
        float x0, x1, x2, x3;
        unpack2(a0, x0, x1); unpack2(a1, x2, x3);
        const float z = xz + ((x0 + x2) + (x1 + x3));
        const float v = gate_act(z, mm, aa, bbv);

        const float fv = __shfl_xor_sync(0xffffffffu, v, 8);
        const float gv = __shfl_xor_sync(0xffffffffu, v, 16);
        const float ov = __shfl_xor_sync(0xffffffffu, v, 24);
        if (q == 0) {
            c = fmaf(fv, c, v * gv);
            const float h = ov * tanh_f(c);
            sh[(t + 1) & 1][j] = h;
            g_hs[((size_t)b * Tq + t) * HDIM + j] = h;
        }
        __syncthreads();
    }
}

// ===========================================================================
// K4: LSTM B recurrence + fused dense tail. Recurrence identical to R10's
// recur_k<1>; afterwards the block computes its row's dense tail from the
// final h (already in smem) — one launch + g_hlast round-trip removed.
// ===========================================================================
__global__ void __launch_bounds__(160)
recur_b_tail(const float* __restrict__ Wr,
             const float* __restrict__ feat,
             const float* __restrict__ Wg, const float* __restrict__ bg,
             const float* __restrict__ Wh, const float* __restrict__ bh,
             const float* __restrict__ Wc, const float* __restrict__ bc,
             const float* __restrict__ Wd, const float* __restrict__ bd,
             const float* __restrict__ Wo, const float* __restrict__ bo,
             float* __restrict__ out)
{
    __shared__ __align__(16) float sxa[8][G4];
    __shared__ __align__(16) float sh[2][HDIM];
    __shared__ float t1[10], yy[10], cc[20], dd[10];

    const int b = blockIdx.x, tid = threadIdx.x;
    const int lane = tid & 31, q = lane >> 3, u = lane & 7, w = tid >> 5;
    const int j = w * 8 + u;
    const int col = q * HDIM + j;

    const bool isG = (q == 2);
    const float mm  = isG ? -2.8853900817779268f : -1.4426950408889634f;
    const float aa  = isG ? 2.0f : 1.0f;
    const float bbv = isG ? -1.0f : 0.0f;

    ull wr2[20];
    #pragma unroll
    for (int p = 0; p < 20; p++)
        wr2[p] = pack2(Wr[(2 * p) * G4 + col], Wr[(2 * p + 1) * G4 + col]);

    float c = 0.0f;
    if (tid < HDIM) sh[0][tid] = 0.0f;

    const float* srcb = g_xb + (size_t)b * Tq * G4;

    if (tid < 40) {
        #pragma unroll
        for (int p = 0; p < 4; p++) {
            unsigned dst = smem_u32(&sxa[p][tid * 4]);
            asm volatile("cp.async.ca.shared.global [%0], [%1], 16;\n\t"
                         "cp.async.commit_group;\n"
                         :: "r"(dst), "l"(srcb + (size_t)p * G4 + tid * 4));
        }
        asm volatile("cp.async.wait_group 3;");
    }
    __syncthreads();

    for (int t = 0; t < Tq; t++) {
        if (tid < 40) {
            const int tf = t + 4;
            if (tf < Tq) {
                unsigned dst = smem_u32(&sxa[tf & 7][tid * 4]);
                asm volatile("cp.async.ca.shared.global [%0], [%1], 16;"
                             :: "r"(dst), "l"(srcb + (size_t)tf * G4 + tid * 4));
            }
            asm volatile("cp.async.commit_group;\n\t"
                         "cp.async.wait_group 3;\n");
        }

        const float xz = sxa[t & 7][col];
        const ulonglong2* h2 = (const ulonglong2*)sh[t & 1];
        ull a0 = 0ull, a1 = 0ull;
        #pragma unroll
        for (int p = 0; p < 10; p++) {
            ulonglong2 hv = h2[p];
            ffma2(a0, wr2[2 * p],     hv.x);
            ffma2(a1, wr2[2 * p + 1], hv.y);
        }
        float x0, x1, x2, x3;
        unpack2(a0, x0, x1); unpack2(a1, x2, x3);
        const float z = xz + ((x0 + x2) + (x1 + x3));
        const float v = gate_act(z, mm, aa, bbv);

        const float fv = __shfl_xor_sync(0xffffffffu, v, 8);
        const float gv = __shfl_xor_sync(0xffffffffu, v, 16);
        const float ov = __shfl_xor_sync(0xffffffffu, v, 24);
        if (q == 0) {
            c = fmaf(fv, c, v * gv);
            sh[(t + 1) & 1][j] = ov * tanh_f(c);
        }
        __syncthreads();
    }

    // ---- fused dense tail for row b (h_last = sh[0], Tq even) ----
    const float* hb = sh[Tq & 1];
    const float* fb = feat + (size_t)b * F_IN;
    if (tid < 10) {
        float a = bg[tid];
        #pragma unroll 8
        for (int k = 0; k < F_IN; k++) a = fmaf(fb[k], Wg[k * 10 + tid], a);
        t1[tid] = tanh_f(a);
    }
    __syncthreads();
    if (tid < 10) {
        float a = bh[tid];
        #pragma unroll
        for (int k = 0; k < 10; k++) a = fmaf(t1[k], Wh[k * 10 + tid], a);
        yy[tid] = tanh_f(a);
    }
    __syncthreads();
    if (tid < 20) {
        float a = bc[tid];
        #pragma unroll
        for (int k = 0; k < HDIM; k++) a = fmaf(hb[k], Wc[k * 20 + tid], a);
        #pragma unroll
        for (int k = 0; k < 10; k++)   a = fmaf(yy[k], Wc[(HDIM + k) * 20 + tid], a);
        cc[tid] = fmaxf(a, 0.0f);
    }
    __syncthreads();
    if (tid < 10) {
        float a = bd[tid];
        #pragma unroll
        for (int k = 0; k < 20; k++) a = fmaf(cc[k], Wd[k * 10 + tid], a);
        dd[tid] = fmaxf(a, 0.0f);
    }
    __syncthreads();
    if (tid == 0) {
        float a = bo[0];
        #pragma unroll
        for (int k = 0; k < 10; k++) a = fmaf(dd[k], Wo[k], a);
        out[b] = sigmoid_f(a);
    }
}

// ---------------------------------------------------------------------------
extern "C" void kernel_launch(void* const* d_in, const int* in_sizes, int n_in,
                              void* d_out, int out_size)
{
    (void)in_sizes; (void)n_in; (void)out_size;
    const float* seq  = (const float*)d_in[0];
    const float* feat = (const float*)d_in[1];
    const float* WaK  = (const float*)d_in[2];
    const float* WaR  = (const float*)d_in[3];
    const float* ba   = (const float*)d_in[4];
    const float* WbK  = (const float*)d_in[5];
    const float* WbR  = (const float*)d_in[6];
    const float* bb   = (const float*)d_in[7];
    const float* Wg   = (const float*)d_in[8];
    const float* bg   = (const float*)d_in[9];
    const float* Wh   = (const float*)d_in[10];
    const float* bh   = (const float*)d_in[11];
    const float* Wc   = (const float*)d_in[12];
    const float* bc   = (const float*)d_in[13];
    const float* Wd   = (const float*)d_in[14];
    const float* bd   = (const float*)d_in[15];
    const float* Wo   = (const float*)d_in[16];
    const float* bo   = (const float*)d_in[17];
    float* out = (float*)d_out;

    xa_gemm<<<dim3(512, 4), 80>>>(seq, WaK, ba);
    recur_a<<<512, 160>>>(WaR);
    xb_gemm<<<dim3(512, 4), 80>>>(WbK, bb);
    recur_b_tail<<<512, 160>>>(WbR, feat, Wg, bg, Wh, bh, Wc, bc,
                               Wd, bd, Wo, bo, out);
}